// round 3
// baseline (speedup 1.0000x reference)
#include <cuda_runtime.h>
#include <cuda_bf16.h>

#define IN_F  256
#define OUT_F 128
#define MAX_N 50048   // a little headroom over 50000

// Scratch (static __device__ — no allocations allowed)
__device__ float g_h[(size_t)MAX_N * OUT_F];   // normalized transformed features
__device__ int   g_deg[MAX_N];                 // out-degree of src nodes

// ---------------------------------------------------------------------------
// Kernel 1: zero degree counters + initialize out = bias broadcast
// ---------------------------------------------------------------------------
__global__ void init_kernel(float* __restrict__ out,
                            const float* __restrict__ bias,
                            int N) {
    int stride = gridDim.x * blockDim.x;
    int tid = blockIdx.x * blockDim.x + threadIdx.x;
    for (int i = tid; i < N; i += stride) g_deg[i] = 0;
    int total = N * OUT_F;
    for (int i = tid; i < total; i += stride) out[i] = bias[i & (OUT_F - 1)];
}

// ---------------------------------------------------------------------------
// Kernel 2: out-degree of src nodes
// ---------------------------------------------------------------------------
__global__ void deg_kernel(const int* __restrict__ src, int E) {
    int stride = gridDim.x * blockDim.x;
    for (int e = blockIdx.x * blockDim.x + threadIdx.x; e < E; e += stride)
        atomicAdd(&g_deg[src[e]], 1);
}

// ---------------------------------------------------------------------------
// Kernel 3: h = (feat @ W) * (1/max(deg,1))   [N,256] x [256,128] -> [N,128]
// Tile: 64 rows x 128 cols per CTA, 256 threads, BK=32.
// A tile stored as duplicated f32x2 pairs (ull) so the inner loop is pure
// fma.rn.f32x2 (packed fp32 FMA, 2x FFMA throughput on sm_103a).
// ---------------------------------------------------------------------------
__global__ void __launch_bounds__(256)
gemm_kernel(const float* __restrict__ feat,
            const float* __restrict__ weight,
            int N) {
    // As2[k][m] = (a, a) packed, row stride 65 for bank-conflict-free stores
    __shared__ unsigned long long As2[32][65];
    // Bs2[k][n/2] = (b_n, b_{n+1}) packed; written as raw float4
    __shared__ unsigned long long Bs2[32][64];

    const int tid = threadIdx.x;
    const int m_id = tid >> 5;   // 0..7  (8 rows of 8 each = 64 rows)
    const int n_id = tid & 31;   // 0..31 (4 cols each = 128 cols)
    const int block_row = blockIdx.x * 64;

    unsigned long long acc01[8], acc23[8];
#pragma unroll
    for (int j = 0; j < 8; j++) { acc01[j] = 0ull; acc23[j] = 0ull; }

    for (int k0 = 0; k0 < IN_F; k0 += 32) {
        // ---- load A tile: 64x32 floats = 512 float4, 2 per thread ----
#pragma unroll
        for (int i = 0; i < 2; i++) {
            int idx = i * 256 + tid;        // 0..511
            int r   = idx >> 3;             // row within tile 0..63
            int kq  = idx & 7;              // which float4 along k
            float4 v = make_float4(0.f, 0.f, 0.f, 0.f);
            int grow = block_row + r;
            if (grow < N)
                v = *(const float4*)(feat + (size_t)grow * IN_F + k0 + kq * 4);
            unsigned long long p0, p1, p2, p3;
            asm("mov.b64 %0, {%1,%1};" : "=l"(p0) : "f"(v.x));
            asm("mov.b64 %0, {%1,%1};" : "=l"(p1) : "f"(v.y));
            asm("mov.b64 %0, {%1,%1};" : "=l"(p2) : "f"(v.z));
            asm("mov.b64 %0, {%1,%1};" : "=l"(p3) : "f"(v.w));
            As2[kq * 4 + 0][r] = p0;
            As2[kq * 4 + 1][r] = p1;
            As2[kq * 4 + 2][r] = p2;
            As2[kq * 4 + 3][r] = p3;
        }
        // ---- load B tile: 32x128 floats = 1024 float4, 4 per thread ----
#pragma unroll
        for (int i = 0; i < 4; i++) {
            int idx = i * 256 + tid;        // 0..1023
            int kr  = idx >> 5;             // k row 0..31
            int nq  = idx & 31;             // which float4 along n
            float4 v = *(const float4*)(weight + (size_t)(k0 + kr) * OUT_F + nq * 4);
            *(float4*)&Bs2[kr][nq * 2] = v; // same bit layout as 2 packed pairs
        }
        __syncthreads();

#pragma unroll
        for (int k = 0; k < 32; k++) {
            ulonglong2 b = *(const ulonglong2*)&Bs2[k][n_id * 2]; // (b0,b1),(b2,b3)
#pragma unroll
            for (int j = 0; j < 8; j++) {
                unsigned long long a2 = As2[k][m_id * 8 + j];     // broadcast
                asm("fma.rn.f32x2 %0, %1, %2, %0;" : "+l"(acc01[j]) : "l"(a2), "l"(b.x));
                asm("fma.rn.f32x2 %0, %1, %2, %0;" : "+l"(acc23[j]) : "l"(a2), "l"(b.y));
            }
        }
        __syncthreads();
    }

    // ---- epilogue: scale by 1/max(deg,1), store to g_h ----
#pragma unroll
    for (int j = 0; j < 8; j++) {
        int grow = block_row + m_id * 8 + j;
        if (grow < N) {
            float norm = 1.0f / fmaxf((float)g_deg[grow], 1.0f);
            float x, y, z, w;
            asm("mov.b64 {%0,%1}, %2;" : "=f"(x), "=f"(y) : "l"(acc01[j]));
            asm("mov.b64 {%0,%1}, %2;" : "=f"(z), "=f"(w) : "l"(acc23[j]));
            float4 o = make_float4(x * norm, y * norm, z * norm, w * norm);
            *(float4*)(g_h + (size_t)grow * OUT_F + n_id * 4) = o;
        }
    }
}

// ---------------------------------------------------------------------------
// Kernel 4: scatter-add  out[dst[e]] += h[src[e]]
// One warp per edge: lane t handles columns [4t, 4t+4) via red.global.add.v4.
// Edges processed in batches of 32 per warp (coalesced index loads + shfl).
// ---------------------------------------------------------------------------
__global__ void __launch_bounds__(256)
scatter_kernel(const int* __restrict__ src,
               const int* __restrict__ dst,
               float* __restrict__ out,
               int E) {
    const int lane  = threadIdx.x & 31;
    const int warp  = (blockIdx.x * blockDim.x + threadIdx.x) >> 5;
    const int nwarp = (gridDim.x * blockDim.x) >> 5;

    for (int base = warp * 32; base < E; base += nwarp * 32) {
        int e = base + lane;
        int s = (e < E) ? src[e] : 0;
        int d = (e < E) ? dst[e] : 0;
        int cnt = E - base; if (cnt > 32) cnt = 32;
        for (int j = 0; j < cnt; j++) {
            int sj = __shfl_sync(0xffffffffu, s, j);
            int dj = __shfl_sync(0xffffffffu, d, j);
            float4 v = *((const float4*)(g_h + (size_t)sj * OUT_F) + lane);
            float* op = out + (size_t)dj * OUT_F + lane * 4;
            asm volatile("red.global.add.v4.f32 [%0], {%1,%2,%3,%4};"
                         :: "l"(op), "f"(v.x), "f"(v.y), "f"(v.z), "f"(v.w)
                         : "memory");
        }
    }
}

// ---------------------------------------------------------------------------
extern "C" void kernel_launch(void* const* d_in, const int* in_sizes, int n_in,
                              void* d_out, int out_size) {
    const float* feat   = (const float*)d_in[0];
    const float* weight = (const float*)d_in[1];
    const float* bias   = (const float*)d_in[2];
    const int*   src    = (const int*)d_in[3];
    const int*   dst    = (const int*)d_in[4];
    float* out = (float*)d_out;

    const int N = in_sizes[0] / IN_F;   // 50000
    const int E = in_sizes[3];          // 800000

    init_kernel<<<1024, 256>>>(out, bias, N);
    deg_kernel<<<512, 256>>>(src, E);
    gemm_kernel<<<(N + 63) / 64, 256>>>(feat, weight, N);
    scatter_kernel<<<2048, 256>>>(src, dst, out, E);
}